// round 5
// baseline (speedup 1.0000x reference)
#include <cuda_runtime.h>

// GaussianKernel: out[b,l,o] = exp(-gamma*(|x[:,l]|^2 + |w[:,o]|^2 - 2 x.w)) + bias[o]
// B=8, K=288, L=16384, O=64.
// Register tile: 4 l x 16 o per thread. Per k: 1 LDG.128 (x, contiguous l),
// 4 broadcast LDS.128 (w), 32+2 FFMA2. LDS per MAC cut 4x vs the 199us baseline;
// fma pipe becomes the limiter (predicted ~75us floor).

#define K_DIM 288
#define O_DIM 64
#define L_DIM 16384
#define B_DIM 8
#define TPB   256
#define TL    4
#define TO    16

#define SMEM_BYTES (K_DIM * O_DIM * 4 + O_DIM * 4 + O_DIM * 4)

__global__ void __launch_bounds__(TPB, 2)
gauss_tile_kernel(const float* __restrict__ x,
                  const float* __restrict__ w,
                  const float* __restrict__ bias,
                  const float* __restrict__ gptr,
                  float* __restrict__ out)
{
    extern __shared__ float sm[];
    float* ws  = sm;                      // [288][64]: wv[k][o] = w_flat[k*64+o]
    float* w2s = sm + K_DIM * O_DIM;      // [64]
    float* bs  = w2s + O_DIM;             // [64]

    const int tid = threadIdx.x;

    for (int i = tid; i < K_DIM * O_DIM; i += TPB) ws[i] = w[i];
    if (tid < O_DIM) bs[tid] = bias[tid];
    __syncthreads();

    if (tid < O_DIM) {
        float s = 0.f;
        #pragma unroll 8
        for (int k = 0; k < K_DIM; k++) {
            float v = ws[k * O_DIM + tid];
            s = fmaf(v, v, s);
        }
        w2s[tid] = s;
    }
    __syncthreads();

    // Thread tile: og selects 16 outputs (constant within each warp -> w LDS
    // is pure warp-broadcast), lt selects 4 consecutive l.
    const int og = tid >> 6;                      // 0..3
    const int lt = tid & 63;                      // 0..63
    const int b  = blockIdx.x >> 6;               // 8 batches, 64 CTAs each
    const int l0 = ((blockIdx.x & 63) * (TPB / 4) + lt) * TL;   // CTA covers 256 l

    const float* xp = x + (size_t)b * K_DIM * L_DIM + l0;

    unsigned long long acc[TL][TO / 2];
    #pragma unroll
    for (int i = 0; i < TL; i++)
        #pragma unroll
        for (int j = 0; j < TO / 2; j++) acc[i][j] = 0ULL;
    unsigned long long x2a = 0ULL, x2b = 0ULL;    // packed |x|^2 for (l0,l1),(l2,l3)

    // 288 = 3*96: unroll 3 -> 3 independent LDG.128 in flight per iteration.
    #pragma unroll 3
    for (int k = 0; k < K_DIM; k++) {
        const float4 xv = __ldg(reinterpret_cast<const float4*>(xp + (size_t)k * L_DIM));

        // packed squares
        unsigned long long x01, x23;
        asm("mov.b64 %0, {%1, %2};" : "=l"(x01) : "f"(xv.x), "f"(xv.y));
        asm("mov.b64 %0, {%1, %2};" : "=l"(x23) : "f"(xv.z), "f"(xv.w));
        asm("fma.rn.f32x2 %0, %1, %1, %0;" : "+l"(x2a) : "l"(x01));
        asm("fma.rn.f32x2 %0, %1, %1, %0;" : "+l"(x2b) : "l"(x23));

        // splats {xl, xl}
        unsigned long long xs[TL];
        asm("mov.b64 %0, {%1, %1};" : "=l"(xs[0]) : "f"(xv.x));
        asm("mov.b64 %0, {%1, %1};" : "=l"(xs[1]) : "f"(xv.y));
        asm("mov.b64 %0, {%1, %1};" : "=l"(xs[2]) : "f"(xv.z));
        asm("mov.b64 %0, {%1, %1};" : "=l"(xs[3]) : "f"(xv.w));

        // w row slice for this o-group: 16 floats = 4 x LDS.128 (broadcast)
        const ulonglong2* wr =
            reinterpret_cast<const ulonglong2*>(ws + k * O_DIM + og * TO);
        #pragma unroll
        for (int q = 0; q < 4; q++) {
            const ulonglong2 wp = wr[q];
            #pragma unroll
            for (int i = 0; i < TL; i++) {
                asm("fma.rn.f32x2 %0, %1, %2, %0;" : "+l"(acc[i][2 * q])     : "l"(xs[i]), "l"(wp.x));
                asm("fma.rn.f32x2 %0, %1, %2, %0;" : "+l"(acc[i][2 * q + 1]) : "l"(xs[i]), "l"(wp.y));
            }
        }
    }

    // Epilogue
    const float ng = -(*gptr);
    float x2v[TL];
    asm("mov.b64 {%0, %1}, %2;" : "=f"(x2v[0]), "=f"(x2v[1]) : "l"(x2a));
    asm("mov.b64 {%0, %1}, %2;" : "=f"(x2v[2]), "=f"(x2v[3]) : "l"(x2b));

    float w2l[TO], bl[TO];
    #pragma unroll
    for (int j = 0; j < TO; j++) { w2l[j] = w2s[og * TO + j]; bl[j] = bs[og * TO + j]; }

    float* op = out + ((size_t)b * L_DIM + l0) * O_DIM + og * TO;
    #pragma unroll
    for (int i = 0; i < TL; i++) {
        float r[TO];
        #pragma unroll
        for (int j = 0; j < TO / 2; j++) {
            float a0, a1;
            asm("mov.b64 {%0, %1}, %2;" : "=f"(a0), "=f"(a1) : "l"(acc[i][j]));
            r[2 * j]     = __expf(ng * (x2v[i] + w2l[2 * j]     - 2.f * a0)) + bl[2 * j];
            r[2 * j + 1] = __expf(ng * (x2v[i] + w2l[2 * j + 1] - 2.f * a1)) + bl[2 * j + 1];
        }
        float4* ov = reinterpret_cast<float4*>(op + (size_t)i * O_DIM);
        ov[0] = make_float4(r[0],  r[1],  r[2],  r[3]);
        ov[1] = make_float4(r[4],  r[5],  r[6],  r[7]);
        ov[2] = make_float4(r[8],  r[9],  r[10], r[11]);
        ov[3] = make_float4(r[12], r[13], r[14], r[15]);
    }
}

extern "C" void kernel_launch(void* const* d_in, const int* in_sizes, int n_in,
                              void* d_out, int out_size)
{
    (void)in_sizes; (void)n_in; (void)out_size;
    const float* x     = (const float*)d_in[0];   // [8, 288, 16384]
    const float* w     = (const float*)d_in[1];   // [64,32,3,3] == flat [288][64]
    const float* bias  = (const float*)d_in[2];   // [64]
    const float* gamma = (const float*)d_in[3];   // scalar
    float* out = (float*)d_out;                   // [8, 16384, 64]

    cudaFuncSetAttribute(gauss_tile_kernel,
                         cudaFuncAttributeMaxDynamicSharedMemorySize, SMEM_BYTES);

    const int grid = (B_DIM * L_DIM) / (TPB / 4 * TL);   // 512 CTAs (256 l each)
    gauss_tile_kernel<<<grid, TPB, SMEM_BYTES>>>(x, w, bias, gamma, out);
}

// round 6
// speedup vs baseline: 1.5718x; 1.5718x over previous
#include <cuda_runtime.h>
#include <cuda_bf16.h>

// GaussianKernel via bf16 tensor-core GEMM:
//   out[b,l,o] = exp(-gamma*(|x[:,l]|^2 + |w[:,o]|^2 - 2 x.w)) + bias[o]
// GEMM view: [M=B*L=131072, N=64, K=288], A = x^T (bf16), B = wv (bf16), C fp32.
// CTA: 128 threads, 64 M-rows, full K resident in smem. mma.sync.m16n8k16.
// |x|^2 kept exact in fp32 (accumulated during load); |w|^2 exact fp32 from gmem.

#define K_DIM   288
#define O_DIM   64
#define L_DIM   16384
#define TPB     128
#define MT      64            // M rows per CTA
#define KSTEPS  18            // 288 / 16
#define A_ROW   292           // bf16 per A row (146 words): conflict-free frag reads

// smem layout (bytes)
#define A_BYTES      (MT * A_ROW * 2)            // 37376
#define WF_WORDS     (KSTEPS * 8 * 32 * 2)       // 9216 words = 36864 B
#define SMEM_A       0
#define SMEM_WF      (A_BYTES)
#define SMEM_X2RED   (SMEM_WF + WF_WORDS * 4)    // [8][64] f32
#define SMEM_X2      (SMEM_X2RED + 8 * 64 * 4)   // [64] f32
#define SMEM_W2      (SMEM_X2 + 64 * 4)          // [64] f32
#define SMEM_TOTAL   (SMEM_W2 + 64 * 4)          // 76800 B

__global__ void __launch_bounds__(TPB)
gauss_mma_kernel(const float* __restrict__ x,
                 const float* __restrict__ w,
                 const float* __restrict__ bias,
                 const float* __restrict__ gptr,
                 float* __restrict__ out)
{
    extern __shared__ char smem[];
    __nv_bfloat16* Ah = (__nv_bfloat16*)(smem + SMEM_A);   // [MT][A_ROW]
    unsigned*      Aw = (unsigned*)(smem + SMEM_A);        // word view
    unsigned*      wf = (unsigned*)(smem + SMEM_WF);       // [18][8][32][2]
    float*      x2red = (float*)(smem + SMEM_X2RED);
    float*        x2s = (float*)(smem + SMEM_X2);
    float*        w2s = (float*)(smem + SMEM_W2);

    const int tid  = threadIdx.x;
    const int lane = tid & 31;
    const int wp   = tid >> 5;
    const int g    = lane >> 2;       // 0..7
    const int t    = lane & 3;        // 0..3

    const int m0 = blockIdx.x * MT;           // 256 CTAs per batch (16384/64)
    const int b  = m0 >> 14;
    const int l0 = m0 & (L_DIM - 1);
    const float* xb = x + (size_t)b * K_DIM * L_DIM + l0;

    // ---- Load A: transpose x[k][l0..l0+63] -> Ah[l][k] bf16, accumulate |x|^2 fp32.
    // thread -> (kslot = tid/16 in 0..7, is = tid%16 covering l = 4*is..4*is+3)
    {
        const int kslot = tid >> 4;
        const int is    = tid & 15;
        float s0 = 0.f, s1 = 0.f, s2 = 0.f, s3 = 0.f;
        __nv_bfloat16* arow = Ah + (4 * is) * A_ROW;
        #pragma unroll 4
        for (int p = 0; p < 36; p++) {
            const int k = p * 8 + kslot;
            const float4 v = __ldg((const float4*)(xb + (size_t)k * L_DIM + 4 * is));
            s0 = fmaf(v.x, v.x, s0);
            s1 = fmaf(v.y, v.y, s1);
            s2 = fmaf(v.z, v.z, s2);
            s3 = fmaf(v.w, v.w, s3);
            arow[0 * A_ROW + k] = __float2bfloat16(v.x);
            arow[1 * A_ROW + k] = __float2bfloat16(v.y);
            arow[2 * A_ROW + k] = __float2bfloat16(v.z);
            arow[3 * A_ROW + k] = __float2bfloat16(v.w);
        }
        float* xr = x2red + kslot * 64 + 4 * is;
        xr[0] = s0; xr[1] = s1; xr[2] = s2; xr[3] = s3;
    }

    // ---- Prepack w into exact m16n8k16 B-fragment layout: wf[s][nb][lane][2].
    // b0 = {wv[k0][n], wv[k0+1][n]}, b1 = {wv[k0+8][n], wv[k0+9][n]},
    // k0 = s*16 + t*2, n = nb*8 + g.
    #pragma unroll 4
    for (int j = 0; j < 36; j++) {
        const int e  = tid + TPB * j;          // 0..4607
        const int T  = e & 31;
        const int nb = (e >> 5) & 7;
        const int s  = e >> 8;
        const int tt = T & 3, gg = T >> 2;
        const int k0 = s * 16 + tt * 2;
        const int n  = nb * 8 + gg;
        const float w00 = w[(size_t)k0 * O_DIM + n];
        const float w01 = w[(size_t)(k0 + 1) * O_DIM + n];
        const float w10 = w[(size_t)(k0 + 8) * O_DIM + n];
        const float w11 = w[(size_t)(k0 + 9) * O_DIM + n];
        __nv_bfloat162 p0 = __float22bfloat162_rn(make_float2(w00, w01));
        __nv_bfloat162 p1 = __float22bfloat162_rn(make_float2(w10, w11));
        wf[e * 2]     = *(unsigned*)&p0;
        wf[e * 2 + 1] = *(unsigned*)&p1;
    }
    __syncthreads();

    // ---- Reductions: tid<64 -> x2; tid in [64,128) -> w2 (exact fp32 from gmem).
    if (tid < 64) {
        float s = 0.f;
        #pragma unroll
        for (int ks = 0; ks < 8; ks++) s += x2red[ks * 64 + tid];
        x2s[tid] = s;
    } else {
        const int o = tid - 64;
        float s = 0.f;
        #pragma unroll 8
        for (int k = 0; k < K_DIM; k++) {
            const float v = w[(size_t)k * O_DIM + o];
            s = fmaf(v, v, s);
        }
        w2s[o] = s;
    }
    __syncthreads();

    // ---- Main GEMM: warp wp covers rows wp*16 + {g, g+8}; 8 n-blocks of 8.
    float c[8][4];
    #pragma unroll
    for (int nb = 0; nb < 8; nb++)
        #pragma unroll
        for (int q = 0; q < 4; q++) c[nb][q] = 0.f;

    const int row = wp * 16 + g;
    #pragma unroll
    for (int s = 0; s < KSTEPS; s++) {
        const unsigned a0 = Aw[(size_t)row       * 146 + s * 8 + t];
        const unsigned a1 = Aw[(size_t)(row + 8) * 146 + s * 8 + t];
        const unsigned a2 = Aw[(size_t)row       * 146 + s * 8 + t + 4];
        const unsigned a3 = Aw[(size_t)(row + 8) * 146 + s * 8 + t + 4];
        const unsigned* wfs = wf + (s * 8) * 64;
        #pragma unroll
        for (int nb = 0; nb < 8; nb++) {
            const uint2 bb = *(const uint2*)(wfs + nb * 64 + lane * 2);
            asm volatile(
                "mma.sync.aligned.m16n8k16.row.col.f32.bf16.bf16.f32 "
                "{%0,%1,%2,%3}, {%4,%5,%6,%7}, {%8,%9}, {%0,%1,%2,%3};\n"
                : "+f"(c[nb][0]), "+f"(c[nb][1]), "+f"(c[nb][2]), "+f"(c[nb][3])
                : "r"(a0), "r"(a1), "r"(a2), "r"(a3), "r"(bb.x), "r"(bb.y));
        }
    }

    // ---- Epilogue: d2 = x2 + w2 - 2*acc; out = exp(-gamma*d2) + bias.
    const float ng  = -(*gptr);
    const float xa  = x2s[row];
    const float xb2 = x2s[row + 8];
    float* orow0 = out + (size_t)(m0 + row)     * O_DIM;
    float* orow1 = out + (size_t)(m0 + row + 8) * O_DIM;
    #pragma unroll
    for (int nb = 0; nb < 8; nb++) {
        const int o  = nb * 8 + t * 2;
        const float w20 = w2s[o],  w21 = w2s[o + 1];
        const float bi0 = __ldg(bias + o), bi1 = __ldg(bias + o + 1);
        float2 r0, r1;
        r0.x = __expf(ng * (xa  + w20 - 2.f * c[nb][0])) + bi0;
        r0.y = __expf(ng * (xa  + w21 - 2.f * c[nb][1])) + bi1;
        r1.x = __expf(ng * (xb2 + w20 - 2.f * c[nb][2])) + bi0;
        r1.y = __expf(ng * (xb2 + w21 - 2.f * c[nb][3])) + bi1;
        *(float2*)(orow0 + o) = r0;
        *(float2*)(orow1 + o) = r1;
    }
}

extern "C" void kernel_launch(void* const* d_in, const int* in_sizes, int n_in,
                              void* d_out, int out_size)
{
    (void)in_sizes; (void)n_in; (void)out_size;
    const float* x     = (const float*)d_in[0];   // [8, 288, 16384]
    const float* w     = (const float*)d_in[1];   // [64,32,3,3] == flat [288][64]
    const float* bias  = (const float*)d_in[2];   // [64]
    const float* gamma = (const float*)d_in[3];   // scalar
    float* out = (float*)d_out;                   // [8, 16384, 64]

    cudaFuncSetAttribute(gauss_mma_kernel,
                         cudaFuncAttributeMaxDynamicSharedMemorySize, SMEM_TOTAL);

    const int grid = (8 * L_DIM) / MT;            // 2048 CTAs
    gauss_mma_kernel<<<grid, TPB, SMEM_TOTAL>>>(x, w, bias, gamma, out);
}

// round 7
// speedup vs baseline: 3.7498x; 2.3857x over previous
#include <cuda_runtime.h>
#include <cuda_bf16.h>

// GaussianKernel via bf16 tensor-core GEMM, round 6:
//   out[b,l,o] = exp(-gamma*(|x|^2 + |w|^2 - 2 x.w)) + bias[o]
// GEMM [M=131072, N=64, K=288]. Changes vs 162us version:
//  - w fragment pack + |w|^2 hoisted to a one-shot init kernel (device globals)
//  - A transpose via STS.64 (4x fewer, 4x wider stores)
//  - |x|^2 via warp butterfly (no smem round trip)
//  - MT=128 rows/CTA, 256 threads, 2 CTAs/SM -> 16 warps/SM
//  - B fragments read as LDS.128 pairs

#define K_DIM   288
#define O_DIM   64
#define L_DIM   16384
#define TPB     256
#define MT      128
#define KSTEPS  18
#define A_PITCH 146                        // words (292 bf16) per A row

#define WF_UINT4 (KSTEPS * 4 * 32)         // 2304 uint4 = 36864 B

__device__ uint4 g_wf[WF_UINT4];           // packed B fragments
__device__ float g_w2[O_DIM];

// smem layout (bytes)
#define A_BYTES   (MT * A_PITCH * 4)       // 74752
#define SMEM_WF   (A_BYTES)
#define SMEM_W2   (SMEM_WF + WF_UINT4 * 16)
#define SMEM_X2   (SMEM_W2 + O_DIM * 4)
#define SMEM_TOT  (SMEM_X2 + MT * 4)       // 112384 B

// ---------------------------------------------------------------------------
// Init: pack w[k][n] (k = row of flat [288][64]) into m16n8k16 B fragments.
// Layout: g_wf[(s*4 + nbp)*32 + lane] = {b0(nb),b1(nb),b0(nb+1),b1(nb+1)},
// nb = 2*nbp; lane: t=lane&3, g=lane>>2; k0 = s*16 + t*2; n = nb*8 + g.
__global__ void gauss_init_kernel(const float* __restrict__ w)
{
    const int e = blockIdx.x * 256 + threadIdx.x;
    if (e < WF_UINT4) {
        const int lane = e & 31, nbp = (e >> 5) & 3, s = e >> 7;
        const int t = lane & 3, g = lane >> 2;
        const int k0 = s * 16 + t * 2;
        const int n0 = (2 * nbp) * 8 + g;
        const int n1 = n0 + 8;
        uint4 r;
        __nv_bfloat162 p;
        p = __float22bfloat162_rn(make_float2(w[(size_t)k0 * O_DIM + n0],
                                              w[(size_t)(k0 + 1) * O_DIM + n0]));
        r.x = *(unsigned*)&p;
        p = __float22bfloat162_rn(make_float2(w[(size_t)(k0 + 8) * O_DIM + n0],
                                              w[(size_t)(k0 + 9) * O_DIM + n0]));
        r.y = *(unsigned*)&p;
        p = __float22bfloat162_rn(make_float2(w[(size_t)k0 * O_DIM + n1],
                                              w[(size_t)(k0 + 1) * O_DIM + n1]));
        r.z = *(unsigned*)&p;
        p = __float22bfloat162_rn(make_float2(w[(size_t)(k0 + 8) * O_DIM + n1],
                                              w[(size_t)(k0 + 9) * O_DIM + n1]));
        r.w = *(unsigned*)&p;
        g_wf[e] = r;
    }
    if (blockIdx.x == 0 && threadIdx.x < O_DIM) {
        float s = 0.f;
        #pragma unroll 8
        for (int k = 0; k < K_DIM; k++) {
            const float v = w[(size_t)k * O_DIM + threadIdx.x];
            s = fmaf(v, v, s);
        }
        g_w2[threadIdx.x] = s;
    }
}

// ---------------------------------------------------------------------------
__global__ void __launch_bounds__(TPB, 2)
gauss_mma_kernel(const float* __restrict__ x,
                 const float* __restrict__ bias,
                 const float* __restrict__ gptr,
                 float* __restrict__ out)
{
    extern __shared__ char smem[];
    unsigned* Aw  = (unsigned*)smem;                 // [MT][A_PITCH] words
    uint4*    wfs = (uint4*)(smem + SMEM_WF);        // [18*4][32]
    float*    w2s = (float*)(smem + SMEM_W2);
    float*    x2s = (float*)(smem + SMEM_X2);

    const int tid  = threadIdx.x;
    const int lane = tid & 31;
    const int wp   = tid >> 5;                       // 0..7

    const int m0 = blockIdx.x * MT;                  // 1024 CTAs
    const int b  = m0 >> 14;
    const int lb = m0 & (L_DIM - 1);
    const float* xb = x + (size_t)b * K_DIM * L_DIM + lb;

    // ---- Copy packed w fragments + w2 to smem (vectorized) ----
    #pragma unroll
    for (int i = 0; i < WF_UINT4 / TPB; i++)         // 9
        wfs[tid + TPB * i] = g_wf[tid + TPB * i];
    if (tid < O_DIM) w2s[tid] = g_w2[tid];

    // ---- Load + transpose A (x^T -> bf16), |x|^2 partials in registers ----
    // lane: j = lane&3 (l sub-group), kc = lane>>2 (k slice).
    // thread: l = 16*wp + 4*j + {0..3};  k = (p*8 + kc)*4 + {0..3}, p = 0..8.
    {
        const int j  = lane & 3;
        const int kc = lane >> 2;
        const int lloc = 16 * wp + 4 * j;
        const float* xp = xb + lloc;
        float s[4] = {0.f, 0.f, 0.f, 0.f};
        #pragma unroll
        for (int p = 0; p < 9; p++) {
            const int k0 = (p * 8 + kc) * 4;
            float4 v[4];
            #pragma unroll
            for (int kk = 0; kk < 4; kk++)
                v[kk] = __ldg((const float4*)(xp + (size_t)(k0 + kk) * L_DIM));
            const float* vp = (const float*)v;       // vp[kk*4 + li]
            #pragma unroll
            for (int li = 0; li < 4; li++) {
                const float f0 = vp[0 * 4 + li], f1 = vp[1 * 4 + li];
                const float f2 = vp[2 * 4 + li], f3 = vp[3 * 4 + li];
                s[li] = fmaf(f0, f0, fmaf(f1, f1, fmaf(f2, f2, fmaf(f3, f3, s[li]))));
                __nv_bfloat162 lo = __float22bfloat162_rn(make_float2(f0, f1));
                __nv_bfloat162 hi = __float22bfloat162_rn(make_float2(f2, f3));
                uint2 pk = make_uint2(*(unsigned*)&lo, *(unsigned*)&hi);
                *(uint2*)(Aw + (size_t)(lloc + li) * A_PITCH + k0 / 2) = pk;
            }
        }
        // butterfly over kc (lane bits 2..4)
        #pragma unroll
        for (int m = 4; m <= 16; m <<= 1)
            #pragma unroll
            for (int li = 0; li < 4; li++)
                s[li] += __shfl_xor_sync(0xffffffffu, s[li], m);
        if (kc == 0) {
            #pragma unroll
            for (int li = 0; li < 4; li++) x2s[lloc + li] = s[li];
        }
    }
    __syncthreads();

    // ---- Main GEMM: warp wp covers rows wp*16 + {g, g+8}; 8 n-blocks ----
    const int g = lane >> 2;
    const int t = lane & 3;
    const int row = wp * 16 + g;

    float c[8][4];
    #pragma unroll
    for (int nb = 0; nb < 8; nb++)
        #pragma unroll
        for (int q = 0; q < 4; q++) c[nb][q] = 0.f;

    #pragma unroll
    for (int s = 0; s < KSTEPS; s++) {
        const unsigned a0 = Aw[(size_t)row       * A_PITCH + s * 8 + t];
        const unsigned a1 = Aw[(size_t)(row + 8) * A_PITCH + s * 8 + t];
        const unsigned a2 = Aw[(size_t)row       * A_PITCH + s * 8 + t + 4];
        const unsigned a3 = Aw[(size_t)(row + 8) * A_PITCH + s * 8 + t + 4];
        #pragma unroll
        for (int nbp = 0; nbp < 4; nbp++) {
            const uint4 bb = wfs[(s * 4 + nbp) * 32 + lane];
            asm volatile(
                "mma.sync.aligned.m16n8k16.row.col.f32.bf16.bf16.f32 "
                "{%0,%1,%2,%3}, {%4,%5,%6,%7}, {%8,%9}, {%0,%1,%2,%3};\n"
                : "+f"(c[2*nbp][0]), "+f"(c[2*nbp][1]), "+f"(c[2*nbp][2]), "+f"(c[2*nbp][3])
                : "r"(a0), "r"(a1), "r"(a2), "r"(a3), "r"(bb.x), "r"(bb.y));
            asm volatile(
                "mma.sync.aligned.m16n8k16.row.col.f32.bf16.bf16.f32 "
                "{%0,%1,%2,%3}, {%4,%5,%6,%7}, {%8,%9}, {%0,%1,%2,%3};\n"
                : "+f"(c[2*nbp+1][0]), "+f"(c[2*nbp+1][1]), "+f"(c[2*nbp+1][2]), "+f"(c[2*nbp+1][3])
                : "r"(a0), "r"(a1), "r"(a2), "r"(a3), "r"(bb.z), "r"(bb.w));
        }
    }

    // ---- Epilogue ----
    const float ng  = -(*gptr);
    const float xa  = x2s[row];
    const float xb2 = x2s[row + 8];
    float* orow0 = out + (size_t)(m0 + row)     * O_DIM;
    float* orow1 = out + (size_t)(m0 + row + 8) * O_DIM;
    #pragma unroll
    for (int nb = 0; nb < 8; nb++) {
        const int o  = nb * 8 + t * 2;
        const float w20 = w2s[o], w21 = w2s[o + 1];
        const float bi0 = __ldg(bias + o), bi1 = __ldg(bias + o + 1);
        float2 r0, r1;
        r0.x = __expf(ng * (xa  + w20 - 2.f * c[nb][0])) + bi0;
        r0.y = __expf(ng * (xa  + w21 - 2.f * c[nb][1])) + bi1;
        r1.x = __expf(ng * (xb2 + w20 - 2.f * c[nb][2])) + bi0;
        r1.y = __expf(ng * (xb2 + w21 - 2.f * c[nb][3])) + bi1;
        *(float2*)(orow0 + o) = r0;
        *(float2*)(orow1 + o) = r1;
    }
}

extern "C" void kernel_launch(void* const* d_in, const int* in_sizes, int n_in,
                              void* d_out, int out_size)
{
    (void)in_sizes; (void)n_in; (void)out_size;
    const float* x     = (const float*)d_in[0];   // [8, 288, 16384]
    const float* w     = (const float*)d_in[1];   // [64,32,3,3] == flat [288][64]
    const float* bias  = (const float*)d_in[2];   // [64]
    const float* gamma = (const float*)d_in[3];   // scalar
    float* out = (float*)d_out;                   // [8, 16384, 64]

    cudaFuncSetAttribute(gauss_mma_kernel,
                         cudaFuncAttributeMaxDynamicSharedMemorySize, SMEM_TOT);

    gauss_init_kernel<<<(WF_UINT4 + 255) / 256, 256>>>(w);
    const int grid = (8 * L_DIM) / MT;            // 1024 CTAs
    gauss_mma_kernel<<<grid, TPB, SMEM_TOT>>>(x, bias, gamma, out);
}